// round 1
// baseline (speedup 1.0000x reference)
#include <cuda_runtime.h>

// DisentangledSelfAttention, fully fused, fp32.
// B=4096 batch, S=64, E=64, A=256, H=4, HD=64. One CTA per batch element.
// Per CTA: stage q/k/v tiles [64x64] in smem; per head stage weight slices,
// compute Qh/Kh/Vh, mean-center Q/K, softmax(QK^T)+unary, AV + residual GEMM.

#define LD 68                      // smem row stride (floats): 16B-aligned rows, odd/32 bank skew
#define SM_FLOATS (7 * 64 * LD + 64 + 64 + 256)

// acc[i][j] += sum_k A[(R+i)*LD+k] * B[k*LD + C+j]     (both row-major in smem)
__device__ __forceinline__ void gemm_nn(const float* __restrict__ A,
                                        const float* __restrict__ B,
                                        float acc[4][4], int R, int C) {
#pragma unroll
    for (int k = 0; k < 64; k += 4) {
        float4 a[4], bb[4];
#pragma unroll
        for (int i = 0; i < 4; i++) a[i] = *(const float4*)&A[(R + i) * LD + k];
#pragma unroll
        for (int kk = 0; kk < 4; kk++) bb[kk] = *(const float4*)&B[(k + kk) * LD + C];
#pragma unroll
        for (int i = 0; i < 4; i++) {
            const float af0 = a[i].x, af1 = a[i].y, af2 = a[i].z, af3 = a[i].w;
            acc[i][0] = fmaf(af0, bb[0].x, acc[i][0]);
            acc[i][1] = fmaf(af0, bb[0].y, acc[i][1]);
            acc[i][2] = fmaf(af0, bb[0].z, acc[i][2]);
            acc[i][3] = fmaf(af0, bb[0].w, acc[i][3]);
            acc[i][0] = fmaf(af1, bb[1].x, acc[i][0]);
            acc[i][1] = fmaf(af1, bb[1].y, acc[i][1]);
            acc[i][2] = fmaf(af1, bb[1].z, acc[i][2]);
            acc[i][3] = fmaf(af1, bb[1].w, acc[i][3]);
            acc[i][0] = fmaf(af2, bb[2].x, acc[i][0]);
            acc[i][1] = fmaf(af2, bb[2].y, acc[i][1]);
            acc[i][2] = fmaf(af2, bb[2].z, acc[i][2]);
            acc[i][3] = fmaf(af2, bb[2].w, acc[i][3]);
            acc[i][0] = fmaf(af3, bb[3].x, acc[i][0]);
            acc[i][1] = fmaf(af3, bb[3].y, acc[i][1]);
            acc[i][2] = fmaf(af3, bb[3].z, acc[i][2]);
            acc[i][3] = fmaf(af3, bb[3].w, acc[i][3]);
        }
    }
}

// acc[i][j] += sum_d A[(R+i)*LD+d] * B[(C+j)*LD+d]     (A @ B^T, both row-major)
__device__ __forceinline__ void gemm_nt(const float* __restrict__ A,
                                        const float* __restrict__ B,
                                        float acc[4][4], int R, int C) {
#pragma unroll
    for (int d = 0; d < 64; d += 4) {
        float4 a[4], bb[4];
#pragma unroll
        for (int i = 0; i < 4; i++) a[i] = *(const float4*)&A[(R + i) * LD + d];
#pragma unroll
        for (int j = 0; j < 4; j++) bb[j] = *(const float4*)&B[(C + j) * LD + d];
#pragma unroll
        for (int i = 0; i < 4; i++) {
#pragma unroll
            for (int j = 0; j < 4; j++) {
                acc[i][j] = fmaf(a[i].x, bb[j].x, acc[i][j]);
                acc[i][j] = fmaf(a[i].y, bb[j].y, acc[i][j]);
                acc[i][j] = fmaf(a[i].z, bb[j].z, acc[i][j]);
                acc[i][j] = fmaf(a[i].w, bb[j].w, acc[i][j]);
            }
        }
    }
}

// dst[e*LD + j] = W[e*256 + hc + j],  e,j in [0,64)
__device__ __forceinline__ void stage_w(float* __restrict__ dst,
                                        const float* __restrict__ W,
                                        int hc, int tid) {
#pragma unroll
    for (int it = 0; it < 4; it++) {
        int i = tid + (it << 8);
        int e = i >> 4, c = (i & 15) << 2;
        *(float4*)&dst[e * LD + c] = *(const float4*)&W[(e << 8) + hc + c];
    }
}

__global__ __launch_bounds__(256, 1)
void disattn_kernel(const float* __restrict__ query,
                    const float* __restrict__ key_,
                    const float* __restrict__ value,
                    const float* __restrict__ Wq, const float* __restrict__ bq,
                    const float* __restrict__ Wk, const float* __restrict__ bk,
                    const float* __restrict__ Wv, const float* __restrict__ bv,
                    const float* __restrict__ Wu, const float* __restrict__ bu,
                    const float* __restrict__ Wr, const float* __restrict__ br,
                    float* __restrict__ out) {
    extern __shared__ float sm[];
    float* sQin = sm;                 // [64][LD] query tile
    float* sKin = sQin + 64 * LD;     // key tile
    float* sVin = sKin + 64 * LD;     // value tile
    float* sW   = sVin + 64 * LD;     // weight slice staging, then scores
    float* sQh  = sW   + 64 * LD;     // Q head
    float* sKh  = sQh  + 64 * LD;     // K head, then Wr slice
    float* sVh  = sKh  + 64 * LD;     // V head
    float* sqm  = sVh  + 64 * LD;     // [64] Q column means
    float* skm  = sqm + 64;           // [64] K column means
    float* susm = skm + 64;           // [4][64] unary softmax

    const int b = blockIdx.x;
    const int tid = threadIdx.x;

    const float* qg = query + (size_t)b * 4096;
    const float* kg = key_  + (size_t)b * 4096;
    const float* vg = value + (size_t)b * 4096;

    // Stage input tiles (coalesced float4).
#pragma unroll
    for (int it = 0; it < 4; it++) {
        int i = tid + (it << 8);
        int r = i >> 4, c = (i & 15) << 2;
        *(float4*)&sQin[r * LD + c] = *(const float4*)&qg[(r << 6) + c];
        *(float4*)&sKin[r * LD + c] = *(const float4*)&kg[(r << 6) + c];
        *(float4*)&sVin[r * LD + c] = *(const float4*)&vg[(r << 6) + c];
    }
    __syncthreads();

    // Unary logits: u[h][s] = key_[s,:] @ Wu[:,h] + bu[h]
    {
        int s = tid & 63, h = tid >> 6;
        float acc = __ldg(&bu[h]);
#pragma unroll
        for (int e = 0; e < 64; e++)
            acc = fmaf(sKin[s * LD + e], __ldg(&Wu[(e << 2) + h]), acc);
        susm[(h << 6) + s] = acc;
    }
    __syncthreads();
    // Softmax over fields s, per head (warp w handles head w).
    {
        int w = tid >> 5, lane = tid & 31;
        if (w < 4) {
            float v0 = susm[(w << 6) + lane];
            float v1 = susm[(w << 6) + lane + 32];
            float m = fmaxf(v0, v1);
#pragma unroll
            for (int d = 16; d; d >>= 1)
                m = fmaxf(m, __shfl_xor_sync(0xffffffffu, m, d));
            float e0 = __expf(v0 - m), e1 = __expf(v1 - m);
            float s2 = e0 + e1;
#pragma unroll
            for (int d = 16; d; d >>= 1)
                s2 += __shfl_xor_sync(0xffffffffu, s2, d);
            float inv = 1.0f / s2;
            susm[(w << 6) + lane]      = e0 * inv;
            susm[(w << 6) + lane + 32] = e1 * inv;
        }
    }
    __syncthreads();

    const int tx = tid & 15, ty = tid >> 4;
    const int R = ty << 2, C = tx << 2;
    float* og = out + (size_t)b * 16384;

#pragma unroll 1
    for (int h = 0; h < 4; h++) {
        const int hc = h << 6;

        // Qh = q_in @ Wq[:,hc:hc+64] + bq
        stage_w(sW, Wq, hc, tid);
        __syncthreads();
        {
            float acc[4][4];
#pragma unroll
            for (int j = 0; j < 4; j++) {
                float bv0 = __ldg(&bq[hc + C + j]);
#pragma unroll
                for (int i = 0; i < 4; i++) acc[i][j] = bv0;
            }
            gemm_nn(sQin, sW, acc, R, C);
#pragma unroll
            for (int i = 0; i < 4; i++) {
                float4 v = make_float4(acc[i][0], acc[i][1], acc[i][2], acc[i][3]);
                *(float4*)&sQh[(R + i) * LD + C] = v;
            }
        }
        __syncthreads();

        // Kh
        stage_w(sW, Wk, hc, tid);
        __syncthreads();
        {
            float acc[4][4];
#pragma unroll
            for (int j = 0; j < 4; j++) {
                float bv0 = __ldg(&bk[hc + C + j]);
#pragma unroll
                for (int i = 0; i < 4; i++) acc[i][j] = bv0;
            }
            gemm_nn(sKin, sW, acc, R, C);
#pragma unroll
            for (int i = 0; i < 4; i++) {
                float4 v = make_float4(acc[i][0], acc[i][1], acc[i][2], acc[i][3]);
                *(float4*)&sKh[(R + i) * LD + C] = v;
            }
        }
        __syncthreads();

        // Vh
        stage_w(sW, Wv, hc, tid);
        __syncthreads();
        {
            float acc[4][4];
#pragma unroll
            for (int j = 0; j < 4; j++) {
                float bv0 = __ldg(&bv[hc + C + j]);
#pragma unroll
                for (int i = 0; i < 4; i++) acc[i][j] = bv0;
            }
            gemm_nn(sVin, sW, acc, R, C);
#pragma unroll
            for (int i = 0; i < 4; i++) {
                float4 v = make_float4(acc[i][0], acc[i][1], acc[i][2], acc[i][3]);
                *(float4*)&sVh[(R + i) * LD + C] = v;
            }
        }
        __syncthreads();

        // Column means of Qh, Kh over the field (row) dimension.
        if (tid < 128) {
            int c = tid & 63;
            const float* src = (tid < 64) ? sQh : sKh;
            float s = 0.0f;
#pragma unroll
            for (int r = 0; r < 64; r++) s += src[r * LD + c];
            ((tid < 64) ? sqm : skm)[c] = s * (1.0f / 64.0f);
        }
        __syncthreads();
#pragma unroll
        for (int it = 0; it < 16; it++) {
            int idx = tid + (it << 8);
            int r = idx >> 6, c = idx & 63;
            sQh[r * LD + c] -= sqm[c];
            sKh[r * LD + c] -= skm[c];
        }
        __syncthreads();

        // scores = Qh @ Kh^T  (into sW; weight staging buffer is dead here)
        {
            float acc[4][4];
#pragma unroll
            for (int i = 0; i < 4; i++)
#pragma unroll
                for (int j = 0; j < 4; j++) acc[i][j] = 0.0f;
            gemm_nt(sQh, sKh, acc, R, C);
#pragma unroll
            for (int i = 0; i < 4; i++) {
                float4 v = make_float4(acc[i][0], acc[i][1], acc[i][2], acc[i][3]);
                *(float4*)&sW[(R + i) * LD + C] = v;
            }
        }
        __syncthreads();

        // Row softmax + unary term. 4 threads per row (16 cols each),
        // groups of 4 lanes are warp-aligned -> shfl_xor 1,2 combine.
        {
            int row = tid >> 2, part = (tid & 3) << 4;
            float* srow = &sW[row * LD + part];
            float m = -1e30f;
#pragma unroll
            for (int c = 0; c < 16; c++) m = fmaxf(m, srow[c]);
            m = fmaxf(m, __shfl_xor_sync(0xffffffffu, m, 1));
            m = fmaxf(m, __shfl_xor_sync(0xffffffffu, m, 2));
            float ssum = 0.0f;
#pragma unroll
            for (int c = 0; c < 16; c++) {
                float e = __expf(srow[c] - m);
                srow[c] = e;
                ssum += e;
            }
            ssum += __shfl_xor_sync(0xffffffffu, ssum, 1);
            ssum += __shfl_xor_sync(0xffffffffu, ssum, 2);
            float inv = 1.0f / ssum;
            const float* uh = &susm[hc + part];
#pragma unroll
            for (int c = 0; c < 16; c++) srow[c] = fmaf(srow[c], inv, uh[c]);
        }
        __syncthreads();

        // Stage Wr slice into sKh (Kh is dead).
        stage_w(sKh, Wr, hc, tid);
        __syncthreads();

        // out = attn @ Vh + q_in @ Wr + br
        {
            float acc[4][4];
#pragma unroll
            for (int j = 0; j < 4; j++) {
                float bv0 = __ldg(&br[hc + C + j]);
#pragma unroll
                for (int i = 0; i < 4; i++) acc[i][j] = bv0;
            }
            gemm_nn(sW, sVh, acc, R, C);
            gemm_nn(sQin, sKh, acc, R, C);
#pragma unroll
            for (int i = 0; i < 4; i++) {
                float4 v = make_float4(acc[i][0], acc[i][1], acc[i][2], acc[i][3]);
                *(float4*)&og[(R + i) * 256 + hc + C] = v;
            }
        }
        __syncthreads();  // before next head restages sW / sKh
    }
}

extern "C" void kernel_launch(void* const* d_in, const int* in_sizes, int n_in,
                              void* d_out, int out_size) {
    const float* query = (const float*)d_in[0];
    const float* key_  = (const float*)d_in[1];
    const float* value = (const float*)d_in[2];
    const float* Wq    = (const float*)d_in[3];
    const float* bq    = (const float*)d_in[4];
    const float* Wk    = (const float*)d_in[5];
    const float* bk    = (const float*)d_in[6];
    const float* Wv    = (const float*)d_in[7];
    const float* bv    = (const float*)d_in[8];
    const float* Wu    = (const float*)d_in[9];
    const float* bu    = (const float*)d_in[10];
    const float* Wr    = (const float*)d_in[11];
    const float* br    = (const float*)d_in[12];
    float* out = (float*)d_out;

    size_t smem = SM_FLOATS * sizeof(float);  // ~123 KB
    cudaFuncSetAttribute(disattn_kernel,
                         cudaFuncAttributeMaxDynamicSharedMemorySize, (int)smem);
    disattn_kernel<<<4096, 256, smem>>>(query, key_, value, Wq, bq, Wk, bk,
                                        Wv, bv, Wu, bu, Wr, br, out);
}